// round 5
// baseline (speedup 1.0000x reference)
#include <cuda_runtime.h>
#include <cuda_bf16.h>
#include <cstdint>

// ScaleLayer: y[b,d] = x[b,d] * exp(diag[d]);  second output = raw diag.
// x: [16384, 4096] fp32 row-major; diag: [4096] fp32.
//
// FINAL (roofline): 512 MiB mandatory HBM traffic (read x + write y) at the
// measured B300 LTS/HBM streaming ceiling (~6.3 TB/s) = ~76 us kernel time.
// Four structural variants (R1-R4) all land 76.0-77.5 us; cache hints and
// MLP>4 were neutral or negative. This is the union of measured-best picks:
//   - exp(diag) precomputed once into a __device__ table (4096 MUFU ops
//     instead of 67M; prologue kernel measured free)
//   - exact-cover, loop-free main kernel: 4 front-batched independent
//     LDG.128 per thread (MLP=4), plain LDG/STG (hints measured neutral),
//     28 regs -> ~80% occupancy, 16384 CTAs x 256 threads.

#define D_DIM 4096
#define B_DIM 16384

__device__ float g_ediag[D_DIM];

__global__ void prep_kernel(const float* __restrict__ diag,
                            float* __restrict__ out_tail,
                            int write_tail) {
    int i = blockIdx.x * blockDim.x + threadIdx.x;
    if (i < D_DIM) {
        float d = diag[i];
        g_ediag[i] = expf(d);
        if (write_tail) out_tail[i] = d;
    }
}

// total4 = 16,777,216 float4.  grid*block = 4,194,304 threads = total4/4.
// Thread j handles {j, j+S, j+2S, j+3S}, S = total threads: exact cover,
// no loop, no tail. S is a multiple of D_DIM/4, so all four elements share
// one exp-table column -> a single L1-resident table load per thread.
__global__ void __launch_bounds__(256)
scale_kernel(const float4* __restrict__ x, float4* __restrict__ y) {
    constexpr int S = (B_DIM * D_DIM) / 4 / 4;     // 4,194,304
    const float4* __restrict__ ed =
        reinterpret_cast<const float4*>(g_ediag);  // 1024 float4 columns

    const int j  = blockIdx.x * blockDim.x + threadIdx.x;
    const int j0 = j;
    const int j1 = j + S;
    const int j2 = j + 2 * S;
    const int j3 = j + 3 * S;

    // Front-batched independent loads (MLP=4).
    float4 v0 = x[j0];
    float4 v1 = x[j1];
    float4 v2 = x[j2];
    float4 v3 = x[j3];

    float4 e = ed[j0 & (D_DIM / 4 - 1)];

    v0.x *= e.x; v0.y *= e.y; v0.z *= e.z; v0.w *= e.w;
    v1.x *= e.x; v1.y *= e.y; v1.z *= e.z; v1.w *= e.w;
    v2.x *= e.x; v2.y *= e.y; v2.z *= e.z; v2.w *= e.w;
    v3.x *= e.x; v3.y *= e.y; v3.z *= e.z; v3.w *= e.w;

    y[j0] = v0;
    y[j1] = v1;
    y[j2] = v2;
    y[j3] = v3;
}

extern "C" void kernel_launch(void* const* d_in, const int* in_sizes, int n_in,
                              void* d_out, int out_size) {
    const float* x    = (const float*)d_in[0];
    const float* diag = (const float*)d_in[1];
    float* out = (float*)d_out;

    const long long n_main = (long long)B_DIM * D_DIM;
    const int write_tail = (out_size > n_main) ? 1 : 0;

    prep_kernel<<<(D_DIM + 255) / 256, 256>>>(diag, out + n_main, write_tail);

    // 16,777,216 float4 / (256 thr * 4 per thread) = 16384 CTAs, exact.
    scale_kernel<<<16384, 256>>>((const float4*)x, (float4*)out);
}

// round 7
// speedup vs baseline: 1.0246x; 1.0246x over previous
#include <cuda_runtime.h>
#include <cuda_bf16.h>
#include <cstdint>

// ScaleLayer: y[b,d] = x[b,d] * exp(diag[d]);  second output = raw diag.
// x: [16384, 4096] fp32 row-major; diag: [4096] fp32.
//
// R7: single-kernel (prep-node overhead removed), echo bug fixed.
// Each thread computes exp() of its own 4 diag entries inline (16.8M EX2
// chip-wide ~= 28us MUFU pipe occupancy, hidden under ~74us of memory
// stalls at issue=8%). Memory pattern identical to measured-best R5:
// exact-cover, loop-free, 4 front-batched LDG.128 per thread (MLP=4),
// plain LDG/STG, 16384 CTAs x 256 threads.
// Diag echo: threads j<1024 (blocks 0-3) write tail[j] = diag4[j], exact
// 1:1 cover of the 4096-float tail (col4 == j there).

#define D_DIM 4096
#define B_DIM 16384

// total4 = 16,777,216 float4.  grid*block = 4,194,304 threads = total4/4.
// Thread j handles {j, j+S, j+2S, j+3S}, S = total threads: exact cover.
// S is a multiple of D_DIM/4, so all four elements share one float4 column.
__global__ void __launch_bounds__(256)
scale_kernel(const float4* __restrict__ x,
             const float4* __restrict__ diag4,
             float4* __restrict__ y,
             float4* __restrict__ tail,   // d_out + B*D (raw diag echo)
             int write_tail) {
    constexpr int S = (B_DIM * D_DIM) / 4 / 4;     // 4,194,304

    const int j  = blockIdx.x * blockDim.x + threadIdx.x;
    const int j0 = j;
    const int j1 = j + S;
    const int j2 = j + 2 * S;
    const int j3 = j + 3 * S;
    const int col4 = j & (D_DIM / 4 - 1);

    // Front-batched independent loads (MLP=4) + the 16B diag load (L1-hot).
    float4 v0 = x[j0];
    float4 v1 = x[j1];
    float4 v2 = x[j2];
    float4 v3 = x[j3];
    float4 d  = diag4[col4];

    // Raw diag echo: threads j<1024 give col4 == j -> exact cover of the
    // 1024-float4 tail by blocks 0..3.
    if (write_tail && j < (D_DIM / 4)) tail[j] = d;

    // exp() inline -- MUFU work overlapped with memory stalls.
    float4 e;
    e.x = expf(d.x);
    e.y = expf(d.y);
    e.z = expf(d.z);
    e.w = expf(d.w);

    v0.x *= e.x; v0.y *= e.y; v0.z *= e.z; v0.w *= e.w;
    v1.x *= e.x; v1.y *= e.y; v1.z *= e.z; v1.w *= e.w;
    v2.x *= e.x; v2.y *= e.y; v2.z *= e.z; v2.w *= e.w;
    v3.x *= e.x; v3.y *= e.y; v3.z *= e.z; v3.w *= e.w;

    y[j0] = v0;
    y[j1] = v1;
    y[j2] = v2;
    y[j3] = v3;
}

extern "C" void kernel_launch(void* const* d_in, const int* in_sizes, int n_in,
                              void* d_out, int out_size) {
    const float* x    = (const float*)d_in[0];
    const float* diag = (const float*)d_in[1];
    float* out = (float*)d_out;

    const long long n_main = (long long)B_DIM * D_DIM;
    const int write_tail = (out_size > n_main) ? 1 : 0;

    // 16,777,216 float4 / (256 thr * 4 per thread) = 16384 CTAs, exact.
    scale_kernel<<<16384, 256>>>((const float4*)x,
                                 (const float4*)diag,
                                 (float4*)out,
                                 (float4*)(out + n_main),
                                 write_tail);
}